// round 1
// baseline (speedup 1.0000x reference)
#include <cuda_runtime.h>
#include <math.h>

#define Nn   50000
#define Ee   800000
#define ETOT 850000
#define HC   256

// ---------------- static device scratch (no allocations allowed) ----------------
__device__ float g_h1[(size_t)Nn * HC];     // 51.2 MB
__device__ float g_h2[(size_t)Nn * HC];     // 51.2 MB
__device__ float g_mid[(size_t)Nn * 64];    // 12.8 MB
__device__ float g_as[Nn * 4];
__device__ float g_ad[Nn * 4];
__device__ int   g_cnt[Nn];
__device__ int   g_incl[Nn];
__device__ int   g_bsum[64];
__device__ int   g_rowptr[Nn + 1];
__device__ int   g_csrc[ETOT];
__device__ int   g_is64;

// ---------------- edge-index dtype detection (int64 vs int32) ----------------
__global__ void k_detect(const long long* ei) {
    __shared__ int bad;
    if (threadIdx.x == 0) bad = 0;
    __syncthreads();
    long long v = ei[threadIdx.x];   // first 256 entries of src row
    if (v < 0 || v >= Nn) atomicExch(&bad, 1);
    __syncthreads();
    if (threadIdx.x == 0) g_is64 = bad ? 0 : 1;
}

__device__ __forceinline__ int edge_at(const void* ei, int which, int i) {
    if (g_is64) return (int)((const long long*)ei)[(size_t)which * Ee + i];
    return ((const int*)ei)[(size_t)which * Ee + i];
}

// ---------------- CSR build (dst-sorted) ----------------
__global__ void k_hist(const void* ei) {
    int i = blockIdx.x * blockDim.x + threadIdx.x;
    if (i >= ETOT) return;
    int d = (i < Ee) ? edge_at(ei, 1, i) : (i - Ee);
    atomicAdd(&g_cnt[d], 1);
}

__global__ void k_scan_block() {
    __shared__ int sh[1024];
    int i = blockIdx.x * 1024 + threadIdx.x;
    int v = (i < Nn) ? g_cnt[i] : 0;
    sh[threadIdx.x] = v;
    __syncthreads();
    for (int off = 1; off < 1024; off <<= 1) {
        int t = (threadIdx.x >= off) ? sh[threadIdx.x - off] : 0;
        __syncthreads();
        sh[threadIdx.x] += t;
        __syncthreads();
    }
    if (i < Nn) g_incl[i] = sh[threadIdx.x];
    if (threadIdx.x == 1023) g_bsum[blockIdx.x] = sh[1023];
}

__global__ void k_scan_bsum(int nb) {
    __shared__ int sh[64];
    int v = (threadIdx.x < nb) ? g_bsum[threadIdx.x] : 0;
    sh[threadIdx.x] = v;
    __syncthreads();
    for (int off = 1; off < 64; off <<= 1) {
        int t = (threadIdx.x >= off) ? sh[threadIdx.x - off] : 0;
        __syncthreads();
        sh[threadIdx.x] += t;
        __syncthreads();
    }
    if (threadIdx.x < nb) g_bsum[threadIdx.x] = sh[threadIdx.x];
}

__global__ void k_scan_add() {
    int i = blockIdx.x * 1024 + threadIdx.x;
    if (i < Nn) {
        int add = blockIdx.x ? g_bsum[blockIdx.x - 1] : 0;
        g_rowptr[i + 1] = g_incl[i] + add;
        if (i == 0) g_rowptr[0] = 0;
    }
}

__global__ void k_scatter(const void* ei) {
    int i = blockIdx.x * blockDim.x + threadIdx.x;
    if (i >= ETOT) return;
    int s, d;
    if (i < Ee) { s = edge_at(ei, 0, i); d = edge_at(ei, 1, i); }
    else        { s = d = i - Ee; }
    int pos = g_rowptr[d] + atomicAdd(&g_cnt[d], 1);
    g_csrc[pos] = s;
}

// ---------------- attention dot products: a_s[n,h] = <h[n,h,:], att_src[h,:]> ----------------
__global__ void k_attn(const float* __restrict__ h,
                       const float* __restrict__ asrc,
                       const float* __restrict__ adst) {
    int n = blockIdx.x;
    int w = threadIdx.x >> 5, l = threadIdx.x & 31;
    const float* hp = h + (size_t)n * HC + w * 64;
    float h0 = hp[l], h1 = hp[l + 32];
    float s = h0 * asrc[w * 64 + l] + h1 * asrc[w * 64 + l + 32];
    float d = h0 * adst[w * 64 + l] + h1 * adst[w * 64 + l + 32];
    for (int o = 16; o; o >>= 1) {
        s += __shfl_xor_sync(0xffffffffu, s, o);
        d += __shfl_xor_sync(0xffffffffu, d, o);
    }
    if (!l) { g_as[n * 4 + w] = s; g_ad[n * 4 + w] = d; }
}

// ---------------- segment softmax + aggregation, fused bias + relu ----------------
// one block per node, warp w = head w, lanes cover 64 channels (l, l+32)
__global__ void k_agg(const float* __restrict__ h,
                      const float* __restrict__ bias,
                      float* __restrict__ out) {
    int n = blockIdx.x;
    int w = threadIdx.x >> 5, l = threadIdx.x & 31;
    int beg = g_rowptr[n], end = g_rowptr[n + 1];
    float adv = g_ad[n * 4 + w];

    // pass 1: segment max (lane-strided)
    float m = -1e30f;
    for (int k = beg + l; k < end; k += 32) {
        int s = g_csrc[k];
        float t = g_as[s * 4 + w] + adv;
        t = (t > 0.f) ? t : 0.2f * t;
        m = fmaxf(m, t);
    }
    for (int o = 16; o; o >>= 1) m = fmaxf(m, __shfl_xor_sync(0xffffffffu, m, o));

    // pass 2: exp weights + weighted feature accumulation (edges in lockstep)
    float a0 = 0.f, a1 = 0.f, den = 0.f;
    for (int k = beg; k < end; ++k) {
        int s = g_csrc[k];
        float t = g_as[s * 4 + w] + adv;
        t = (t > 0.f) ? t : 0.2f * t;
        float wt = __expf(t - m);
        den += wt;
        const float* hp = h + (size_t)s * HC + w * 64;
        a0 += wt * hp[l];
        a1 += wt * hp[l + 32];
    }
    float inv = 1.f / (den + 1e-16f);
    size_t o = (size_t)n * HC + w * 64;
    out[o + l]      = fmaxf(a0 * inv + bias[w * 64 + l], 0.f);
    out[o + l + 32] = fmaxf(a1 * inv + bias[w * 64 + l + 32], 0.f);
}

// ---------------- tiled SGEMM: C[M,Ncol] = A[M,K] @ B[K,Ncol] (+bias, +act) ----------------
// BM=BN=64, BK=16, 256 threads, 4x4 per thread. ACT: 0 none, 1 sigmoid.
template <int ACT>
__global__ void k_gemm(const float* __restrict__ A, const float* __restrict__ B,
                       const float* __restrict__ bias, float* __restrict__ C,
                       int M, int K, int Ncol) {
    __shared__ float As[16][64];
    __shared__ float Bs[16][64];
    int tid = threadIdx.x;
    int tx = tid & 15, ty = tid >> 4;
    int rowBase = blockIdx.y * 64, colBase = blockIdx.x * 64;
    float acc[4][4] = {};

    for (int k0 = 0; k0 < K; k0 += 16) {
#pragma unroll
        for (int i = 0; i < 4; i++) {
            int idx = tid + i * 256;
            int m = idx >> 4, kk = idx & 15;
            int gr = rowBase + m;
            As[kk][m] = (gr < M) ? A[(size_t)gr * K + k0 + kk] : 0.f;
        }
#pragma unroll
        for (int i = 0; i < 4; i++) {
            int idx = tid + i * 256;
            int kk = idx >> 6, nl = idx & 63;
            int gc = colBase + nl;
            Bs[kk][nl] = (gc < Ncol) ? B[(size_t)(k0 + kk) * Ncol + gc] : 0.f;
        }
        __syncthreads();
#pragma unroll
        for (int kk = 0; kk < 16; kk++) {
            float4 av = *(const float4*)&As[kk][ty * 4];
            float4 bv = *(const float4*)&Bs[kk][tx * 4];
            float a[4] = {av.x, av.y, av.z, av.w};
            float b[4] = {bv.x, bv.y, bv.z, bv.w};
#pragma unroll
            for (int i = 0; i < 4; i++)
#pragma unroll
                for (int j = 0; j < 4; j++) acc[i][j] += a[i] * b[j];
        }
        __syncthreads();
    }

#pragma unroll
    for (int i = 0; i < 4; i++) {
        int gr = rowBase + ty * 4 + i;
        if (gr >= M) continue;
#pragma unroll
        for (int j = 0; j < 4; j++) {
            int gc = colBase + tx * 4 + j;
            if (gc >= Ncol) continue;
            float v = acc[i][j];
            if (bias) v += bias[gc];
            if (ACT == 1) v = 1.f / (1.f + __expf(-v));
            C[(size_t)gr * Ncol + gc] = v;
        }
    }
}

// ---------------- launch ----------------
extern "C" void kernel_launch(void* const* d_in, const int* in_sizes, int n_in,
                              void* d_out, int out_size) {
    const float* x   = (const float*)d_in[0];
    const void*  ei  = d_in[1];                 // int64 or int32, detected on device
    const float* W1  = (const float*)d_in[2];
    const float* as1 = (const float*)d_in[3];
    const float* ad1 = (const float*)d_in[4];
    const float* b1  = (const float*)d_in[5];
    const float* W2  = (const float*)d_in[6];
    const float* as2 = (const float*)d_in[7];
    const float* ad2 = (const float*)d_in[8];
    const float* b2  = (const float*)d_in[9];
    const float* Wm1 = (const float*)d_in[10];
    const float* bm1 = (const float*)d_in[11];
    const float* Wm2 = (const float*)d_in[12];
    const float* bm2 = (const float*)d_in[13];
    float* out = (float*)d_out;

    void* cntp; cudaGetSymbolAddress(&cntp, g_cnt);
    float *h1, *h2, *mid;
    cudaGetSymbolAddress((void**)&h1, g_h1);
    cudaGetSymbolAddress((void**)&h2, g_h2);
    cudaGetSymbolAddress((void**)&mid, g_mid);

    // --- CSR build ---
    k_detect<<<1, 256>>>((const long long*)ei);
    cudaMemsetAsync(cntp, 0, Nn * sizeof(int));
    k_hist<<<(ETOT + 255) / 256, 256>>>(ei);
    k_scan_block<<<49, 1024>>>();
    k_scan_bsum<<<1, 64>>>(49);
    k_scan_add<<<49, 1024>>>();
    cudaMemsetAsync(cntp, 0, Nn * sizeof(int));
    k_scatter<<<(ETOT + 255) / 256, 256>>>(ei);

    dim3 gHC((HC + 63) / 64, (Nn + 63) / 64);
    // --- layer 1 ---
    k_gemm<0><<<gHC, 256>>>(x, W1, nullptr, h1, Nn, 128, HC);
    k_attn<<<Nn, 128>>>(h1, as1, ad1);
    k_agg<<<Nn, 128>>>(h1, b1, h2);
    // --- layer 2 ---
    k_gemm<0><<<gHC, 256>>>(h2, W2, nullptr, h1, Nn, HC, HC);
    k_attn<<<Nn, 128>>>(h1, as2, ad2);
    k_agg<<<Nn, 128>>>(h1, b2, h2);
    // --- MLP head ---
    dim3 gM1((64 + 63) / 64, (Nn + 63) / 64);
    k_gemm<0><<<gM1, 256>>>(h2, Wm1, bm1, mid, Nn, HC, 64);
    dim3 gM2((121 + 63) / 64, (Nn + 63) / 64);
    k_gemm<1><<<gM2, 256>>>(mid, Wm2, bm2, out, Nn, 64, 121);
}

// round 2
// speedup vs baseline: 1.0075x; 1.0075x over previous
#include <cuda_runtime.h>
#include <math.h>

#define Nn   50000
#define Ee   800000
#define ETOT 850000
#define HC   256

// ---------------- static device scratch (no allocations allowed) ----------------
__device__ float g_h1[(size_t)Nn * HC];     // 51.2 MB
__device__ float g_h2[(size_t)Nn * HC];     // 51.2 MB
__device__ float g_mid[(size_t)Nn * 64];    // 12.8 MB
__device__ float g_as[Nn * 4];
__device__ float g_ad[Nn * 4];
__device__ int   g_cnt[Nn];
__device__ int   g_incl[Nn];
__device__ int   g_bsum[64];
__device__ int   g_rowptr[Nn + 1];
__device__ int   g_csrc[ETOT];
__device__ int   g_is64;

// ---------------- edge-index dtype detection (int64 vs int32) ----------------
__global__ void k_detect(const long long* ei) {
    __shared__ int bad;
    if (threadIdx.x == 0) bad = 0;
    __syncthreads();
    long long v = ei[threadIdx.x];
    if (v < 0 || v >= Nn) atomicExch(&bad, 1);
    __syncthreads();
    if (threadIdx.x == 0) g_is64 = bad ? 0 : 1;
}

__device__ __forceinline__ int edge_at(const void* ei, int which, int i) {
    if (g_is64) return (int)((const long long*)ei)[(size_t)which * Ee + i];
    return ((const int*)ei)[(size_t)which * Ee + i];
}

// ---------------- CSR build (dst-sorted) ----------------
__global__ void k_hist(const void* ei) {
    int i = blockIdx.x * blockDim.x + threadIdx.x;
    if (i >= ETOT) return;
    int d = (i < Ee) ? edge_at(ei, 1, i) : (i - Ee);
    atomicAdd(&g_cnt[d], 1);
}

__global__ void k_scan_block() {
    __shared__ int sh[1024];
    int i = blockIdx.x * 1024 + threadIdx.x;
    int v = (i < Nn) ? g_cnt[i] : 0;
    sh[threadIdx.x] = v;
    __syncthreads();
    for (int off = 1; off < 1024; off <<= 1) {
        int t = (threadIdx.x >= off) ? sh[threadIdx.x - off] : 0;
        __syncthreads();
        sh[threadIdx.x] += t;
        __syncthreads();
    }
    if (i < Nn) g_incl[i] = sh[threadIdx.x];
    if (threadIdx.x == 1023) g_bsum[blockIdx.x] = sh[1023];
}

__global__ void k_scan_bsum(int nb) {
    __shared__ int sh[64];
    int v = (threadIdx.x < nb) ? g_bsum[threadIdx.x] : 0;
    sh[threadIdx.x] = v;
    __syncthreads();
    for (int off = 1; off < 64; off <<= 1) {
        int t = (threadIdx.x >= off) ? sh[threadIdx.x - off] : 0;
        __syncthreads();
        sh[threadIdx.x] += t;
        __syncthreads();
    }
    if (threadIdx.x < nb) g_bsum[threadIdx.x] = sh[threadIdx.x];
}

__global__ void k_scan_add() {
    int i = blockIdx.x * 1024 + threadIdx.x;
    if (i < Nn) {
        int add = blockIdx.x ? g_bsum[blockIdx.x - 1] : 0;
        g_rowptr[i + 1] = g_incl[i] + add;
        if (i == 0) g_rowptr[0] = 0;
    }
}

__global__ void k_scatter(const void* ei) {
    int i = blockIdx.x * blockDim.x + threadIdx.x;
    if (i >= ETOT) return;
    int s, d;
    if (i < Ee) { s = edge_at(ei, 0, i); d = edge_at(ei, 1, i); }
    else        { s = d = i - Ee; }
    int pos = g_rowptr[d] + atomicAdd(&g_cnt[d], 1);
    g_csrc[pos] = s;
}

// ---------------- attention dot products ----------------
__global__ void k_attn(const float* __restrict__ h,
                       const float* __restrict__ asrc,
                       const float* __restrict__ adst) {
    int n = blockIdx.x;
    int w = threadIdx.x >> 5, l = threadIdx.x & 31;
    const float* hp = h + (size_t)n * HC + w * 64;
    float h0 = hp[l], h1 = hp[l + 32];
    float s = h0 * asrc[w * 64 + l] + h1 * asrc[w * 64 + l + 32];
    float d = h0 * adst[w * 64 + l] + h1 * adst[w * 64 + l + 32];
    for (int o = 16; o; o >>= 1) {
        s += __shfl_xor_sync(0xffffffffu, s, o);
        d += __shfl_xor_sync(0xffffffffu, d, o);
    }
    if (!l) { g_as[n * 4 + w] = s; g_ad[n * 4 + w] = d; }
}

// ---------------- segment softmax + aggregation, fused bias + relu ----------------
__global__ void k_agg(const float* __restrict__ h,
                      const float* __restrict__ bias,
                      float* __restrict__ out) {
    int n = blockIdx.x;
    int w = threadIdx.x >> 5, l = threadIdx.x & 31;
    int beg = g_rowptr[n], end = g_rowptr[n + 1];
    float adv = g_ad[n * 4 + w];

    float m = -1e30f;
    for (int k = beg + l; k < end; k += 32) {
        int s = g_csrc[k];
        float t = g_as[s * 4 + w] + adv;
        t = (t > 0.f) ? t : 0.2f * t;
        m = fmaxf(m, t);
    }
    for (int o = 16; o; o >>= 1) m = fmaxf(m, __shfl_xor_sync(0xffffffffu, m, o));

    float a0 = 0.f, a1 = 0.f, den = 0.f;
    for (int k = beg; k < end; ++k) {
        int s = g_csrc[k];
        float t = g_as[s * 4 + w] + adv;
        t = (t > 0.f) ? t : 0.2f * t;
        float wt = __expf(t - m);
        den += wt;
        const float* hp = h + (size_t)s * HC + w * 64;
        a0 += wt * hp[l];
        a1 += wt * hp[l + 32];
    }
    float inv = 1.f / (den + 1e-16f);
    size_t o = (size_t)n * HC + w * 64;
    out[o + l]      = fmaxf(a0 * inv + bias[w * 64 + l], 0.f);
    out[o + l + 32] = fmaxf(a1 * inv + bias[w * 64 + l + 32], 0.f);
}

// ---------------- double-buffered tiled SGEMM ----------------
// C[M,N] = A[M,K] @ B[K,N] (+bias)(+sigmoid). 256 threads.
// (BM/TM)*(BN/TN) == 256. K % BK == 0 required.
template <int BM, int BN, int BK, int TM, int TN, int ACT, bool VECB>
__global__ __launch_bounds__(256)
void k_gemm2(const float* __restrict__ A, const float* __restrict__ B,
             const float* __restrict__ bias, float* __restrict__ C,
             int M, int K, int N) {
    constexpr int LDA = BM + 4;
    constexpr int LDB = BN + 4;
    constexpr int NA4 = BM * BK / 1024;           // float4 A loads / thread / step
    constexpr int NB4 = (BK * BN / 1024 > 0) ? BK * BN / 1024 : 1;
    constexpr int NBS = BK * BN / 256;            // scalar B loads / thread / step

    __shared__ float As[2][BK][LDA];
    __shared__ float Bs[2][BK][LDB];

    const int tid = threadIdx.x;
    const int tx = tid % (BN / TN);
    const int ty = tid / (BN / TN);
    const int rowBase = blockIdx.y * BM;
    const int colBase = blockIdx.x * BN;

    float acc[TM][TN] = {};
    float4 pa[NA4];
    float4 pb4[NB4];
    float  pbs[NBS];

    const int nsteps = K / BK;

    // ---- prologue: fetch step 0 ----
#pragma unroll
    for (int i = 0; i < NA4; i++) {
        int f = tid + i * 256;
        int row = f / (BK / 4), kq = f % (BK / 4);
        int gr = rowBase + row;
        pa[i] = (gr < M) ? *(const float4*)&A[(size_t)gr * K + kq * 4]
                         : make_float4(0.f, 0.f, 0.f, 0.f);
    }
    if (VECB) {
#pragma unroll
        for (int i = 0; i < NB4; i++) {
            int f = tid + i * 256;
            int k = f / (BN / 4), cq = f % (BN / 4);
            int gc = colBase + cq * 4;
            pb4[i] = (gc + 3 < N) ? *(const float4*)&B[(size_t)k * N + gc]
                                  : make_float4(0.f, 0.f, 0.f, 0.f);
        }
    } else {
#pragma unroll
        for (int i = 0; i < NBS; i++) {
            int f = tid + i * 256;
            int k = f / BN, c = f % BN;
            int gc = colBase + c;
            pbs[i] = (gc < N) ? B[(size_t)k * N + gc] : 0.f;
        }
    }
    // store to buffer 0
#pragma unroll
    for (int i = 0; i < NA4; i++) {
        int f = tid + i * 256;
        int row = f / (BK / 4), kq = f % (BK / 4);
        As[0][kq * 4 + 0][row] = pa[i].x;
        As[0][kq * 4 + 1][row] = pa[i].y;
        As[0][kq * 4 + 2][row] = pa[i].z;
        As[0][kq * 4 + 3][row] = pa[i].w;
    }
    if (VECB) {
#pragma unroll
        for (int i = 0; i < NB4; i++) {
            int f = tid + i * 256;
            int k = f / (BN / 4), cq = f % (BN / 4);
            *(float4*)&Bs[0][k][cq * 4] = pb4[i];
        }
    } else {
#pragma unroll
        for (int i = 0; i < NBS; i++) {
            int f = tid + i * 256;
            int k = f / BN, c = f % BN;
            Bs[0][k][c] = pbs[i];
        }
    }
    __syncthreads();

    // ---- main loop ----
    for (int s = 0; s < nsteps; ++s) {
        int buf = s & 1;
        int k0n = (s + 1) * BK;
        bool more = (s + 1 < nsteps);

        // prefetch next step into registers
        if (more) {
#pragma unroll
            for (int i = 0; i < NA4; i++) {
                int f = tid + i * 256;
                int row = f / (BK / 4), kq = f % (BK / 4);
                int gr = rowBase + row;
                pa[i] = (gr < M) ? *(const float4*)&A[(size_t)gr * K + k0n + kq * 4]
                                 : make_float4(0.f, 0.f, 0.f, 0.f);
            }
            if (VECB) {
#pragma unroll
                for (int i = 0; i < NB4; i++) {
                    int f = tid + i * 256;
                    int k = f / (BN / 4), cq = f % (BN / 4);
                    int gc = colBase + cq * 4;
                    pb4[i] = (gc + 3 < N) ? *(const float4*)&B[(size_t)(k0n + k) * N + gc]
                                          : make_float4(0.f, 0.f, 0.f, 0.f);
                }
            } else {
#pragma unroll
                for (int i = 0; i < NBS; i++) {
                    int f = tid + i * 256;
                    int k = f / BN, c = f % BN;
                    int gc = colBase + c;
                    pbs[i] = (gc < N) ? B[(size_t)(k0n + k) * N + gc] : 0.f;
                }
            }
        }

        // compute on current buffer
#pragma unroll
        for (int kk = 0; kk < BK; kk++) {
            float a[TM], b[TN];
#pragma unroll
            for (int i = 0; i < TM / 4; i++) {
                float4 v = *(const float4*)&As[buf][kk][ty * TM + i * 4];
                a[i * 4 + 0] = v.x; a[i * 4 + 1] = v.y; a[i * 4 + 2] = v.z; a[i * 4 + 3] = v.w;
            }
#pragma unroll
            for (int j = 0; j < TN / 4; j++) {
                float4 v = *(const float4*)&Bs[buf][kk][tx * TN + j * 4];
                b[j * 4 + 0] = v.x; b[j * 4 + 1] = v.y; b[j * 4 + 2] = v.z; b[j * 4 + 3] = v.w;
            }
#pragma unroll
            for (int i = 0; i < TM; i++)
#pragma unroll
                for (int j = 0; j < TN; j++) acc[i][j] += a[i] * b[j];
        }

        // store prefetched regs into the other buffer
        if (more) {
            int nb = buf ^ 1;
#pragma unroll
            for (int i = 0; i < NA4; i++) {
                int f = tid + i * 256;
                int row = f / (BK / 4), kq = f % (BK / 4);
                As[nb][kq * 4 + 0][row] = pa[i].x;
                As[nb][kq * 4 + 1][row] = pa[i].y;
                As[nb][kq * 4 + 2][row] = pa[i].z;
                As[nb][kq * 4 + 3][row] = pa[i].w;
            }
            if (VECB) {
#pragma unroll
                for (int i = 0; i < NB4; i++) {
                    int f = tid + i * 256;
                    int k = f / (BN / 4), cq = f % (BN / 4);
                    *(float4*)&Bs[nb][k][cq * 4] = pb4[i];
                }
            } else {
#pragma unroll
                for (int i = 0; i < NBS; i++) {
                    int f = tid + i * 256;
                    int k = f / BN, c = f % BN;
                    Bs[nb][k][c] = pbs[i];
                }
            }
        }
        __syncthreads();
    }

    // ---- epilogue ----
#pragma unroll
    for (int i = 0; i < TM; i++) {
        int gr = rowBase + ty * TM + i;
        if (gr >= M) continue;
#pragma unroll
        for (int j = 0; j < TN; j++) {
            int gc = colBase + tx * TN + j;
            if (gc >= N) continue;
            float v = acc[i][j];
            if (bias) v += bias[gc];
            if (ACT == 1) v = 1.f / (1.f + __expf(-v));
            C[(size_t)gr * N + gc] = v;
        }
    }
}

// ---------------- launch ----------------
extern "C" void kernel_launch(void* const* d_in, const int* in_sizes, int n_in,
                              void* d_out, int out_size) {
    const float* x   = (const float*)d_in[0];
    const void*  ei  = d_in[1];
    const float* W1  = (const float*)d_in[2];
    const float* as1 = (const float*)d_in[3];
    const float* ad1 = (const float*)d_in[4];
    const float* b1  = (const float*)d_in[5];
    const float* W2  = (const float*)d_in[6];
    const float* as2 = (const float*)d_in[7];
    const float* ad2 = (const float*)d_in[8];
    const float* b2  = (const float*)d_in[9];
    const float* Wm1 = (const float*)d_in[10];
    const float* bm1 = (const float*)d_in[11];
    const float* Wm2 = (const float*)d_in[12];
    const float* bm2 = (const float*)d_in[13];
    float* out = (float*)d_out;

    void* cntp; cudaGetSymbolAddress(&cntp, g_cnt);
    float *h1, *h2, *mid;
    cudaGetSymbolAddress((void**)&h1, g_h1);
    cudaGetSymbolAddress((void**)&h2, g_h2);
    cudaGetSymbolAddress((void**)&mid, g_mid);

    // --- CSR build ---
    k_detect<<<1, 256>>>((const long long*)ei);
    cudaMemsetAsync(cntp, 0, Nn * sizeof(int));
    k_hist<<<(ETOT + 255) / 256, 256>>>(ei);
    k_scan_block<<<49, 1024>>>();
    k_scan_bsum<<<1, 64>>>(49);
    k_scan_add<<<49, 1024>>>();
    cudaMemsetAsync(cntp, 0, Nn * sizeof(int));
    k_scatter<<<(ETOT + 255) / 256, 256>>>(ei);

    const int MB = (Nn + 127) / 128;  // 391

    // --- layer 1: h1 = x @ W1 ---
    k_gemm2<128, 128, 16, 8, 8, 0, true><<<dim3(2, MB), 256>>>(x, W1, nullptr, h1, Nn, 128, HC);
    k_attn<<<Nn, 128>>>(h1, as1, ad1);
    k_agg<<<Nn, 128>>>(h1, b1, h2);
    // --- layer 2: h1 = h2 @ W2 ---
    k_gemm2<128, 128, 16, 8, 8, 0, true><<<dim3(2, MB), 256>>>(h2, W2, nullptr, h1, Nn, HC, HC);
    k_attn<<<Nn, 128>>>(h1, as2, ad2);
    k_agg<<<Nn, 128>>>(h1, b2, h2);
    // --- MLP head ---
    k_gemm2<128, 64, 16, 8, 4, 0, true><<<dim3(1, MB), 256>>>(h2, Wm1, bm1, mid, Nn, HC, 64);
    k_gemm2<128, 128, 16, 8, 8, 1, false><<<dim3(1, MB), 256>>>(mid, Wm2, bm2, out, Nn, 64, 121);
}

// round 3
// speedup vs baseline: 1.4361x; 1.4255x over previous
#include <cuda_runtime.h>
#include <cuda_bf16.h>
#include <math.h>

#define Nn   50000
#define Ee   800000
#define ETOT 850000
#define HC   256

typedef __nv_bfloat16 bf16;

// ---------------- static device scratch ----------------
__device__ __align__(16) bf16  g_ax[(size_t)Nn * 384];     // x ext        38.4 MB
__device__ __align__(16) bf16  g_aext[(size_t)Nn * 768];   // h ext        76.8 MB
__device__ __align__(16) bf16  g_midext[(size_t)Nn * 192]; // mid ext      19.2 MB
__device__ __align__(16) float g_h1[(size_t)Nn * HC];      // fp32 GEMM out 51.2 MB
__device__ __align__(16) bf16  g_b1e[384 * 256];
__device__ __align__(16) bf16  g_b2e[768 * 256];
__device__ __align__(16) bf16  g_b3e[768 * 64];
__device__ __align__(16) bf16  g_b4e[192 * 128];
__device__ float g_as[Nn * 4];
__device__ float g_ad[Nn * 4];
__device__ int   g_cnt[Nn];
__device__ int   g_incl[Nn];
__device__ int   g_bsum[64];
__device__ int   g_rowptr[Nn + 1];
__device__ int   g_csrc[ETOT];
__device__ int   g_is64;

// ---------------- edge-index dtype detection ----------------
__global__ void k_detect(const long long* ei) {
    __shared__ int bad;
    if (threadIdx.x == 0) bad = 0;
    __syncthreads();
    long long v = ei[threadIdx.x];
    if (v < 0 || v >= Nn) atomicExch(&bad, 1);
    __syncthreads();
    if (threadIdx.x == 0) g_is64 = bad ? 0 : 1;
}

__device__ __forceinline__ int edge_at(const void* ei, int which, int i) {
    if (g_is64) return (int)((const long long*)ei)[(size_t)which * Ee + i];
    return ((const int*)ei)[(size_t)which * Ee + i];
}

// ---------------- CSR build ----------------
__global__ void k_hist(const void* ei) {
    int i = blockIdx.x * blockDim.x + threadIdx.x;
    if (i >= ETOT) return;
    int d = (i < Ee) ? edge_at(ei, 1, i) : (i - Ee);
    atomicAdd(&g_cnt[d], 1);
}

__global__ void k_scan_block() {
    __shared__ int sh[1024];
    int i = blockIdx.x * 1024 + threadIdx.x;
    int v = (i < Nn) ? g_cnt[i] : 0;
    sh[threadIdx.x] = v;
    __syncthreads();
    for (int off = 1; off < 1024; off <<= 1) {
        int t = (threadIdx.x >= off) ? sh[threadIdx.x - off] : 0;
        __syncthreads();
        sh[threadIdx.x] += t;
        __syncthreads();
    }
    if (i < Nn) g_incl[i] = sh[threadIdx.x];
    if (threadIdx.x == 1023) g_bsum[blockIdx.x] = sh[1023];
}

__global__ void k_scan_bsum(int nb) {
    __shared__ int sh[64];
    int v = (threadIdx.x < nb) ? g_bsum[threadIdx.x] : 0;
    sh[threadIdx.x] = v;
    __syncthreads();
    for (int off = 1; off < 64; off <<= 1) {
        int t = (threadIdx.x >= off) ? sh[threadIdx.x - off] : 0;
        __syncthreads();
        sh[threadIdx.x] += t;
        __syncthreads();
    }
    if (threadIdx.x < nb) g_bsum[threadIdx.x] = sh[threadIdx.x];
}

__global__ void k_scan_add() {
    int i = blockIdx.x * 1024 + threadIdx.x;
    if (i < Nn) {
        int add = blockIdx.x ? g_bsum[blockIdx.x - 1] : 0;
        g_rowptr[i + 1] = g_incl[i] + add;
        if (i == 0) g_rowptr[0] = 0;
    }
}

__global__ void k_scatter(const void* ei) {
    int i = blockIdx.x * blockDim.x + threadIdx.x;
    if (i >= ETOT) return;
    int s, d;
    if (i < Ee) { s = edge_at(ei, 0, i); d = edge_at(ei, 1, i); }
    else        { s = d = i - Ee; }
    int pos = g_rowptr[d] + atomicAdd(&g_cnt[d], 1);
    g_csrc[pos] = s;
}

// ---------------- split-bf16 conversions ----------------
__device__ __forceinline__ void split_bf(float v, bf16& hi, bf16& lo) {
    hi = __float2bfloat16(v);
    lo = __float2bfloat16(v - __bfloat162float(hi));
}

// A ext: cols [0,K)=hi, [K,2K)=lo, [2K,3K)=hi
__global__ void k_convA(const float* __restrict__ X, bf16* __restrict__ out, int M, int K) {
    int idx = blockIdx.x * blockDim.x + threadIdx.x;
    if (idx >= M * K) return;
    int m = idx / K, k = idx % K;
    bf16 hi, lo;
    split_bf(X[idx], hi, lo);
    size_t base = (size_t)m * (3 * K);
    out[base + k] = hi;
    out[base + K + k] = lo;
    out[base + 2 * K + k] = hi;
}

// B ext: rows [0,K)=hi, [K,2K)=hi, [2K,3K)=lo ; pads cols to Nphys with 0
__global__ void k_convB(const float* __restrict__ W, bf16* __restrict__ out,
                        int K, int Nsrc, int Nphys) {
    int idx = blockIdx.x * blockDim.x + threadIdx.x;
    if (idx >= K * Nphys) return;
    int k = idx / Nphys, n = idx % Nphys;
    float v = (n < Nsrc) ? W[k * Nsrc + n] : 0.f;
    bf16 hi, lo;
    split_bf(v, hi, lo);
    out[(size_t)k * Nphys + n] = hi;
    out[(size_t)(K + k) * Nphys + n] = hi;
    out[(size_t)(2 * K + k) * Nphys + n] = lo;
}

// ---------------- attention dot products ----------------
__global__ void k_attn(const float* __restrict__ h,
                       const float* __restrict__ asrc,
                       const float* __restrict__ adst) {
    int n = blockIdx.x;
    int w = threadIdx.x >> 5, l = threadIdx.x & 31;
    const float* hp = h + (size_t)n * HC + w * 64;
    float h0 = hp[l], h1 = hp[l + 32];
    float s = h0 * asrc[w * 64 + l] + h1 * asrc[w * 64 + l + 32];
    float d = h0 * adst[w * 64 + l] + h1 * adst[w * 64 + l + 32];
    for (int o = 16; o; o >>= 1) {
        s += __shfl_xor_sync(0xffffffffu, s, o);
        d += __shfl_xor_sync(0xffffffffu, d, o);
    }
    if (!l) { g_as[n * 4 + w] = s; g_ad[n * 4 + w] = d; }
}

// ---------------- segment softmax + aggregation + bias + relu -> ext bf16 ----------------
// ext layout per row (768): [0,256)=hi, [256,512)=lo, [512,768)=hi
__global__ void k_agg(const float* __restrict__ h,
                      const float* __restrict__ bias,
                      bf16* __restrict__ outext) {
    int n = blockIdx.x;
    int w = threadIdx.x >> 5, l = threadIdx.x & 31;
    int beg = g_rowptr[n], end = g_rowptr[n + 1];
    float adv = g_ad[n * 4 + w];

    float m = -1e30f;
    for (int k = beg + l; k < end; k += 32) {
        int s = g_csrc[k];
        float t = g_as[s * 4 + w] + adv;
        t = (t > 0.f) ? t : 0.2f * t;
        m = fmaxf(m, t);
    }
    for (int o = 16; o; o >>= 1) m = fmaxf(m, __shfl_xor_sync(0xffffffffu, m, o));

    float a0 = 0.f, a1 = 0.f, den = 0.f;
    for (int k = beg; k < end; ++k) {
        int s = g_csrc[k];
        float t = g_as[s * 4 + w] + adv;
        t = (t > 0.f) ? t : 0.2f * t;
        float wt = __expf(t - m);
        den += wt;
        const float* hp = h + (size_t)s * HC + w * 64;
        a0 += wt * hp[l];
        a1 += wt * hp[l + 32];
    }
    float inv = 1.f / (den + 1e-16f);
    float v0 = fmaxf(a0 * inv + bias[w * 64 + l], 0.f);
    float v1 = fmaxf(a1 * inv + bias[w * 64 + l + 32], 0.f);
    size_t base = (size_t)n * 768;
    int c0 = w * 64 + l, c1 = c0 + 32;
    bf16 h0, l0, h1b, l1;
    split_bf(v0, h0, l0);
    split_bf(v1, h1b, l1);
    outext[base + c0] = h0;  outext[base + 256 + c0] = l0;  outext[base + 512 + c0] = h0;
    outext[base + c1] = h1b; outext[base + 256 + c1] = l1;  outext[base + 512 + c1] = h1b;
}

// ---------------- tensor-core bf16 GEMM (mma.sync m16n8k16) ----------------
__device__ __forceinline__ unsigned smem_u32(const void* p) {
    return (unsigned)__cvta_generic_to_shared(p);
}
__device__ __forceinline__ void ldsm4(unsigned addr, unsigned& r0, unsigned& r1,
                                      unsigned& r2, unsigned& r3) {
    asm volatile("ldmatrix.sync.aligned.m8n8.x4.shared.b16 {%0,%1,%2,%3},[%4];"
                 : "=r"(r0), "=r"(r1), "=r"(r2), "=r"(r3) : "r"(addr));
}
__device__ __forceinline__ void ldsm4t(unsigned addr, unsigned& r0, unsigned& r1,
                                       unsigned& r2, unsigned& r3) {
    asm volatile("ldmatrix.sync.aligned.m8n8.x4.trans.shared.b16 {%0,%1,%2,%3},[%4];"
                 : "=r"(r0), "=r"(r1), "=r"(r2), "=r"(r3) : "r"(addr));
}
__device__ __forceinline__ void mma16816(float& c0, float& c1, float& c2, float& c3,
                                         unsigned a0, unsigned a1, unsigned a2, unsigned a3,
                                         unsigned b0, unsigned b1) {
    asm volatile("mma.sync.aligned.m16n8k16.row.col.f32.bf16.bf16.f32 "
                 "{%0,%1,%2,%3},{%4,%5,%6,%7},{%8,%9},{%0,%1,%2,%3};"
                 : "+f"(c0), "+f"(c1), "+f"(c2), "+f"(c3)
                 : "r"(a0), "r"(a1), "r"(a2), "r"(a3), "r"(b0), "r"(b1));
}

// BM=128, BK=32, 256 threads (8 warps). BN in {128,64}.
// WM warps along M, MF = 128/(WM*16) m16-frags per warp, 8 n8-frags per warp.
// OUTMODE: 0 raw fp32; 1 fp32 bias+sigmoid; 2 ext-bf16 bias (row = 3*Nlog)
template <int BN, int WM, int MF, int OUTMODE>
__global__ __launch_bounds__(256)
void k_gmma(const bf16* __restrict__ A, const bf16* __restrict__ B,
            const float* __restrict__ bias, void* __restrict__ Cout,
            int M, int Kext, int NB, int Nlog) {
    constexpr int LDA = 40;          // 32 + 8 pad (bf16)
    constexpr int LDB = BN + 8;
    constexpr int NB4 = BN * 32 / 2048;   // int4 B loads / thread / stage (2 or 1)

    __shared__ bf16 As[2][128 * LDA];
    __shared__ bf16 Bs[2][32 * LDB];

    const int tid = threadIdx.x;
    const int warp = tid >> 5, lane = tid & 31;
    const int wm = warp % WM, wn = warp / WM;
    const int warpRow = wm * (MF * 16);
    const int warpCol = wn * 64;
    const int rowBase = blockIdx.y * 128;
    const int colBase = blockIdx.x * BN;

    float acc[MF][8][4];
#pragma unroll
    for (int i = 0; i < MF; i++)
#pragma unroll
        for (int j = 0; j < 8; j++)
#pragma unroll
            for (int q = 0; q < 4; q++) acc[i][j][q] = 0.f;

    const int nsteps = Kext / 32;
    int4 pa[2], pb[NB4];

    // ---- prologue: load stage 0 directly ----
#pragma unroll
    for (int i = 0; i < 2; i++) {
        int idx = tid + i * 256;              // 512 int4 = 128 rows x 4
        int row = idx >> 2, q = idx & 3;
        int gr = rowBase + row;
        int4 v = (gr < M) ? *(const int4*)(A + (size_t)gr * Kext + q * 8)
                          : make_int4(0, 0, 0, 0);
        *(int4*)(&As[0][row * LDA + q * 8]) = v;
    }
#pragma unroll
    for (int i = 0; i < NB4; i++) {
        int idx = tid + i * 256;
        int k = idx / (BN / 8), q = idx % (BN / 8);
        int4 v = *(const int4*)(B + (size_t)k * NB + colBase + q * 8);
        *(int4*)(&Bs[0][k * LDB + q * 8]) = v;
    }
    __syncthreads();

    for (int s = 0; s < nsteps; ++s) {
        int buf = s & 1;
        bool more = (s + 1 < nsteps);
        int k0n = (s + 1) * 32;

        if (more) {
#pragma unroll
            for (int i = 0; i < 2; i++) {
                int idx = tid + i * 256;
                int row = idx >> 2, q = idx & 3;
                int gr = rowBase + row;
                pa[i] = (gr < M) ? *(const int4*)(A + (size_t)gr * Kext + k0n + q * 8)
                                 : make_int4(0, 0, 0, 0);
            }
#pragma unroll
            for (int i = 0; i < NB4; i++) {
                int idx = tid + i * 256;
                int k = idx / (BN / 8), q = idx % (BN / 8);
                pb[i] = *(const int4*)(B + (size_t)(k0n + k) * NB + colBase + q * 8);
            }
        }

        unsigned aB = smem_u32(&As[buf][0]);
        unsigned bB = smem_u32(&Bs[buf][0]);

#pragma unroll
        for (int ks = 0; ks < 32; ks += 16) {
            unsigned a[MF][4];
#pragma unroll
            for (int mf = 0; mf < MF; mf++) {
                int row = warpRow + mf * 16 + (lane & 7) + ((lane & 8) ? 8 : 0);
                int col = ks + ((lane & 16) ? 8 : 0);
                ldsm4(aB + (row * LDA + col) * 2, a[mf][0], a[mf][1], a[mf][2], a[mf][3]);
            }
            unsigned bb[8][2];
#pragma unroll
            for (int g = 0; g < 4; g++) {
                int kk = ks + (lane & 7) + ((lane & 8) ? 8 : 0);
                int nn = warpCol + g * 16 + ((lane & 16) ? 8 : 0);
                unsigned r0, r1, r2, r3;
                ldsm4t(bB + (kk * LDB + nn) * 2, r0, r1, r2, r3);
                bb[2 * g][0] = r0; bb[2 * g][1] = r1;
                bb[2 * g + 1][0] = r2; bb[2 * g + 1][1] = r3;
            }
#pragma unroll
            for (int mf = 0; mf < MF; mf++)
#pragma unroll
                for (int nf = 0; nf < 8; nf++)
                    mma16816(acc[mf][nf][0], acc[mf][nf][1], acc[mf][nf][2], acc[mf][nf][3],
                             a[mf][0], a[mf][1], a[mf][2], a[mf][3],
                             bb[nf][0], bb[nf][1]);
        }

        if (more) {
            int nb = buf ^ 1;
#pragma unroll
            for (int i = 0; i < 2; i++) {
                int idx = tid + i * 256;
                int row = idx >> 2, q = idx & 3;
                *(int4*)(&As[nb][row * LDA + q * 8]) = pa[i];
            }
#pragma unroll
            for (int i = 0; i < NB4; i++) {
                int idx = tid + i * 256;
                int k = idx / (BN / 8), q = idx % (BN / 8);
                *(int4*)(&Bs[nb][k * LDB + q * 8]) = pb[i];
            }
        }
        __syncthreads();
    }

    // ---- epilogue ----
#pragma unroll
    for (int mf = 0; mf < MF; mf++) {
#pragma unroll
        for (int nf = 0; nf < 8; nf++) {
            int gr0 = rowBase + warpRow + mf * 16 + (lane >> 2);
            int gc  = colBase + warpCol + nf * 8 + (lane & 3) * 2;
#pragma unroll
            for (int half = 0; half < 2; half++) {
                int gr = gr0 + half * 8;
                if (gr >= M) continue;
                float v0 = acc[mf][nf][half * 2 + 0];
                float v1 = acc[mf][nf][half * 2 + 1];
                if (OUTMODE == 0) {
                    float* C = (float*)Cout;
                    C[(size_t)gr * Nlog + gc] = v0;
                    C[(size_t)gr * Nlog + gc + 1] = v1;
                } else if (OUTMODE == 1) {
                    float* C = (float*)Cout;
                    if (gc < Nlog)
                        C[(size_t)gr * Nlog + gc] = 1.f / (1.f + __expf(-(v0 + bias[gc])));
                    if (gc + 1 < Nlog)
                        C[(size_t)gr * Nlog + gc + 1] = 1.f / (1.f + __expf(-(v1 + bias[gc + 1])));
                } else {
                    bf16* C = (bf16*)Cout;
                    size_t base = (size_t)gr * (3 * Nlog);
                    float w0 = v0 + bias[gc], w1 = v1 + bias[gc + 1];
                    bf16 h0, l0, h1, l1;
                    split_bf(w0, h0, l0);
                    split_bf(w1, h1, l1);
                    C[base + gc] = h0; C[base + Nlog + gc] = l0; C[base + 2 * Nlog + gc] = h0;
                    C[base + gc + 1] = h1; C[base + Nlog + gc + 1] = l1; C[base + 2 * Nlog + gc + 1] = h1;
                }
            }
        }
    }
}

// ---------------- launch ----------------
extern "C" void kernel_launch(void* const* d_in, const int* in_sizes, int n_in,
                              void* d_out, int out_size) {
    const float* x   = (const float*)d_in[0];
    const void*  ei  = d_in[1];
    const float* W1  = (const float*)d_in[2];
    const float* as1 = (const float*)d_in[3];
    const float* ad1 = (const float*)d_in[4];
    const float* b1  = (const float*)d_in[5];
    const float* W2  = (const float*)d_in[6];
    const float* as2 = (const float*)d_in[7];
    const float* ad2 = (const float*)d_in[8];
    const float* b2  = (const float*)d_in[9];
    const float* Wm1 = (const float*)d_in[10];
    const float* bm1 = (const float*)d_in[11];
    const float* Wm2 = (const float*)d_in[12];
    const float* bm2 = (const float*)d_in[13];
    float* out = (float*)d_out;

    void* cntp; cudaGetSymbolAddress(&cntp, g_cnt);
    bf16 *ax, *aext, *midext, *b1e, *b2e, *b3e, *b4e;
    float* h1;
    cudaGetSymbolAddress((void**)&ax, g_ax);
    cudaGetSymbolAddress((void**)&aext, g_aext);
    cudaGetSymbolAddress((void**)&midext, g_midext);
    cudaGetSymbolAddress((void**)&h1, g_h1);
    cudaGetSymbolAddress((void**)&b1e, g_b1e);
    cudaGetSymbolAddress((void**)&b2e, g_b2e);
    cudaGetSymbolAddress((void**)&b3e, g_b3e);
    cudaGetSymbolAddress((void**)&b4e, g_b4e);

    // --- CSR build ---
    k_detect<<<1, 256>>>((const long long*)ei);
    cudaMemsetAsync(cntp, 0, Nn * sizeof(int));
    k_hist<<<(ETOT + 255) / 256, 256>>>(ei);
    k_scan_block<<<49, 1024>>>();
    k_scan_bsum<<<1, 64>>>(49);
    k_scan_add<<<49, 1024>>>();
    cudaMemsetAsync(cntp, 0, Nn * sizeof(int));
    k_scatter<<<(ETOT + 255) / 256, 256>>>(ei);

    // --- operand conversions ---
    k_convA<<<(Nn * 128 + 255) / 256, 256>>>(x, ax, Nn, 128);
    k_convB<<<(128 * 256 + 255) / 256, 256>>>(W1, b1e, 128, 256, 256);
    k_convB<<<(256 * 256 + 255) / 256, 256>>>(W2, b2e, 256, 256, 256);
    k_convB<<<(256 * 64 + 255) / 256, 256>>>(Wm1, b3e, 256, 64, 64);
    k_convB<<<(64 * 128 + 255) / 256, 256>>>(Wm2, b4e, 64, 121, 128);

    const int MB = (Nn + 127) / 128;  // 391

    // --- layer 1: h1 = x @ W1 ---
    k_gmma<128, 4, 2, 0><<<dim3(2, MB), 256>>>(ax, b1e, nullptr, h1, Nn, 384, 256, 256);
    k_attn<<<Nn, 128>>>(h1, as1, ad1);
    k_agg<<<Nn, 128>>>(h1, b1, aext);
    // --- layer 2 ---
    k_gmma<128, 4, 2, 0><<<dim3(2, MB), 256>>>(aext, b2e, nullptr, h1, Nn, 768, 256, 256);
    k_attn<<<Nn, 128>>>(h1, as2, ad2);
    k_agg<<<Nn, 128>>>(h1, b2, aext);
    // --- MLP head ---
    k_gmma<64, 8, 1, 2><<<dim3(1, MB), 256>>>(aext, b3e, bm1, midext, Nn, 768, 64, 64);
    k_gmma<128, 4, 2, 1><<<dim3(1, MB), 256>>>(midext, b4e, bm2, out, Nn, 192, 128, 121);
}